// round 11
// baseline (speedup 1.0000x reference)
#include <cuda_runtime.h>
#include <math.h>

#define BS   32
#define SS   2048
#define FF   512
#define RAD  12
#define KW   25
#define TAPS 26
#define STILE 16
#define CHUNK 8            // s-values per thread in setup kernel (256 thr)

// Scratch (no cudaMalloc allowed): combined 26-tap weights and base row per s.
__device__ float g_cw[SS * TAPS];
__device__ int   g_base[SS];

// Level offsets for the associative-scan pyramid (sizes 2048,1024,...,1).
__constant__ int c_off[12] = {0, 2048, 3072, 3584, 3840, 3968, 4032,
                              4064, 4080, 4088, 4092, 4094};

// ---------------------------------------------------------------------------
// Kernel A: tiny MLP (f32) -> tanh -> softplus (jax formula) -> f32
// ASSOCIATIVE-SCAN cumsum replicating XLA's exact add-pairing (the loss is
// sensitive to the cumsum's specific f32 rounding realization, so we must
// reproduce the reference's bit pattern, not merely its precision class)
// -> warp positions + combined smoothing/interp weights + smoothness loss.
// ---------------------------------------------------------------------------
__global__ __launch_bounds__(256)
void warp_setup_kernel(const float* __restrict__ W1,
                       const float* __restrict__ b1,
                       const float* __restrict__ W2,
                       const float* __restrict__ b2,
                       float* __restrict__ loss_out,
                       int write_loss)
{
    __shared__ float lv[4095];        // scan pyramid, 16 KB
    __shared__ float wf[SS];          // f32 warp values
    __shared__ float skern[KW];
    __shared__ double red[8];

    const int tid  = threadIdx.x;     // 0..255
    const int lane = tid & 31;
    const int wrp  = tid >> 5;

    if (tid == 0) {
        double kd[KW], sum = 0.0;
        for (int m = 0; m < KW; m++) {
            double xx = (double)(m - RAD) / 3.0;
            kd[m] = exp(-0.5 * xx * xx);
            sum += kd[m];
        }
        for (int m = 0; m < KW; m++) skern[m] = (float)(kd[m] / sum);
    }

    // --- f32 MLP, tanh, softplus (jax: max(w,0)+log1p(exp(-|w|))) per s ---
    for (int i = 0; i < CHUNK; i++) {
        const int s = i * 256 + tid;
        const float t = (float)s / (float)(SS - 1);
        float acc = b2[0];
        for (int j = 0; j < 64; j++) {
            float h = fmaf(t, W1[j], b1[j]);
            h = fmaxf(h, 0.0f);
            acc = fmaf(h, W2[j], acc);
        }
        const float w  = tanhf(acc);                       // in [-1, 1]
        const float sp = fmaxf(w, 0.0f) + log1pf(expf(-fabsf(w)));
        lv[s] = sp;
    }
    __syncthreads();

    // --- up-sweep: pairwise sums, 11 levels (matches jax associative_scan) ---
    for (int k = 0; k < 11; k++) {
        const int half = (SS >> k) >> 1;
        const int o  = c_off[k];
        const int o1 = c_off[k + 1];
        for (int j = tid; j < half; j += 256)
            lv[o1 + j] = lv[o + 2 * j] + lv[o + 2 * j + 1];
        __syncthreads();
    }

    // --- down-sweep: scan[k][2j+1] = scan[k+1][j];
    //                 scan[k][2j]   = scan[k+1][j-1] + level[k][2j] (j>=1);
    //                 scan[k][0]    = level[k][0] (already in place) ---
    for (int k = 10; k >= 0; k--) {
        const int half = (SS >> k) >> 1;
        const int o  = c_off[k];
        const int o1 = c_off[k + 1];
        for (int j = tid; j < half; j += 256) {
            const float sn = lv[o1 + j];
            if (j >= 1) lv[o + 2 * j] = lv[o1 + j - 1] + lv[o + 2 * j];
            lv[o + 2 * j + 1] = sn;
        }
        __syncthreads();
    }

    const float total = lv[SS - 1];

    // --- per-s warp value (f32 IEEE divide, like ref), base, weights ---
    for (int i = 0; i < CHUNK; i++) {
        const int s = i * 256 + tid;
        const float w1f = lv[s] / total;
        wf[s] = w1f;
        const float pos = w1f * (float)(SS - 1);
        float fi0 = floorf(pos);
        if (fi0 < 0.0f) fi0 = 0.0f;
        if (fi0 > (float)(SS - 2)) fi0 = (float)(SS - 2);
        const int   i0   = (int)fi0;
        const float frac = pos - fi0;
        const float om   = 1.0f - frac;
        g_base[s] = i0 - RAD;
        #pragma unroll
        for (int m = 0; m < TAPS; m++) {
            const float k0 = (m < KW) ? skern[m]     : 0.0f;
            const float k1 = (m >= 1) ? skern[m - 1] : 0.0f;
            g_cw[s * TAPS + m] = om * k0 + frac * k1;
        }
    }
    __syncthreads();

    // --- smoothness loss: mean squared f32 2nd difference of warps ---
    double ssq = 0.0;
    for (int i = 0; i < CHUNK; i++) {
        const int s = i * 256 + tid;
        if (s <= SS - 3) {
            const float d1a = wf[s + 1] - wf[s];
            const float d1b = wf[s + 2] - wf[s + 1];
            const float d2  = d1b - d1a;
            ssq += (double)d2 * (double)d2;
        }
    }
    for (int off = 16; off; off >>= 1)
        ssq += __shfl_down_sync(0xffffffffu, ssq, off);
    if (lane == 0) red[wrp] = ssq;
    __syncthreads();
    if (tid == 0 && write_loss) {
        double v = 0.0;
        for (int wv = 0; wv < 8; wv++) v += red[wv];
        *loss_out = (float)(v / (double)(SS - 2));
    }
}

// ---------------------------------------------------------------------------
// Kernel B: fused smooth + warp interp. One CTA = 1 batch x 16 s-rows x 512 f.
// 256 threads: tx&127 -> float4 feature column, tx>>7 -> s phase (2 phases).
// 26-tap weighted sum of input rows with symmetric reflection at borders.
// ---------------------------------------------------------------------------
__global__ __launch_bounds__(256)
void warp_apply_kernel(const float* __restrict__ x, float* __restrict__ out)
{
    __shared__ float swt[STILE * TAPS];   // 416 weights
    __shared__ int   sbase[STILE];

    const int b  = blockIdx.y;
    const int s0 = blockIdx.x * STILE;
    const int tx = threadIdx.x;

    for (int i = tx; i < STILE * TAPS; i += 256) swt[i] = g_cw[s0 * TAPS + i];
    if (tx < STILE) sbase[tx] = g_base[s0 + tx];
    __syncthreads();

    const int f4 = tx & 127;       // which float4 column (128 * 4 = 512 feats)
    const int sp = tx >> 7;        // 0 or 1

    const float4* __restrict__ xb =
        (const float4*)(x + (size_t)b * SS * FF);
    float4* __restrict__ ob =
        (float4*)(out + (size_t)b * SS * FF);

    for (int ss = sp; ss < STILE; ss += 2) {
        const int base = sbase[ss];
        const float* wt = &swt[ss * TAPS];
        float4 acc = make_float4(0.f, 0.f, 0.f, 0.f);
        #pragma unroll
        for (int m = 0; m < TAPS; m++) {
            int r = base + m;
            r = (r < 0) ? (-1 - r) : ((r >= SS) ? (2 * SS - 1 - r) : r);
            float4 v = __ldg(xb + (size_t)r * (FF / 4) + f4);
            const float w = wt[m];
            acc.x = fmaf(w, v.x, acc.x);
            acc.y = fmaf(w, v.y, acc.y);
            acc.z = fmaf(w, v.z, acc.z);
            acc.w = fmaf(w, v.w, acc.w);
        }
        ob[(size_t)(s0 + ss) * (FF / 4) + f4] = acc;
    }
}

extern "C" void kernel_launch(void* const* d_in, const int* in_sizes, int n_in,
                              void* d_out, int out_size)
{
    const float* x  = (const float*)d_in[0];
    const float* W1 = (const float*)d_in[1];
    const float* b1 = (const float*)d_in[2];
    const float* W2 = (const float*)d_in[3];
    const float* b2 = (const float*)d_in[4];
    float* out = (float*)d_out;

    const size_t warped_elems = (size_t)BS * SS * FF;
    const int write_loss = ((size_t)out_size > warped_elems) ? 1 : 0;
    float* loss_ptr = out + warped_elems;   // scalar loss after warped tensor

    warp_setup_kernel<<<1, 256>>>(W1, b1, W2, b2, loss_ptr, write_loss);

    dim3 grid(SS / STILE, BS);
    warp_apply_kernel<<<grid, 256>>>(x, out);
}

// round 12
// speedup vs baseline: 1.3327x; 1.3327x over previous
#include <cuda_runtime.h>
#include <math.h>

#define BS   32
#define SS   2048
#define FF   512
#define RAD  12
#define KW   25
#define TAPS 26
#define STILE 16
#define CHUNK 8            // s-values per thread in setup kernel (256 thr)
#define SPAN 96            // max input-row window per 8-s group (bound ~60)

// Scratch (no cudaMalloc allowed): combined 26-tap weights and base row per s.
__device__ float g_cw[SS * TAPS];
__device__ int   g_base[SS];

// Level offsets for the associative-scan pyramid (sizes 2048,1024,...,1).
__constant__ int c_off[12] = {0, 2048, 3072, 3584, 3840, 3968, 4032,
                              4064, 4080, 4088, 4092, 4094};

// packed fp32x2 fma (per-lane IEEE identical to fmaf)
#define FMA_X2(acc, w, v) \
    asm("fma.rn.f32x2 %0, %1, %2, %0;" : "+l"(acc) : "l"(w), "l"(v))

// ---------------------------------------------------------------------------
// Kernel A: tiny MLP (f32, j-outer loop: weights loaded once per j) -> tanh ->
// softplus -> f32 ASSOCIATIVE-SCAN cumsum replicating XLA's exact add-pairing
// -> warp positions + combined smoothing/interp weights + smoothness loss.
// All arithmetic bit-identical to the R11 passing version.
// ---------------------------------------------------------------------------
__global__ __launch_bounds__(256)
void warp_setup_kernel(const float* __restrict__ W1,
                       const float* __restrict__ b1,
                       const float* __restrict__ W2,
                       const float* __restrict__ b2,
                       float* __restrict__ loss_out,
                       int write_loss)
{
    __shared__ float lv[4095];        // scan pyramid, 16 KB
    __shared__ float wf[SS];          // f32 warp values
    __shared__ float skern[KW];
    __shared__ double red[8];

    const int tid  = threadIdx.x;     // 0..255
    const int lane = tid & 31;
    const int wrp  = tid >> 5;

    if (tid == 0) {
        double kd[KW], sum = 0.0;
        for (int m = 0; m < KW; m++) {
            double xx = (double)(m - RAD) / 3.0;
            kd[m] = exp(-0.5 * xx * xx);
            sum += kd[m];
        }
        for (int m = 0; m < KW; m++) skern[m] = (float)(kd[m] / sum);
    }

    // --- f32 MLP: j-outer so W1/b1/W2 are loaded once per j (8x fewer LDG).
    //     Per-element arithmetic order identical to j-inner version. ---
    float tv[CHUNK], accv[CHUNK];
    #pragma unroll
    for (int i = 0; i < CHUNK; i++) {
        tv[i]   = (float)(i * 256 + tid) / (float)(SS - 1);
        accv[i] = b2[0];
    }
    for (int j = 0; j < 64; j++) {
        const float w1 = W1[j], bb = b1[j], w2 = W2[j];
        #pragma unroll
        for (int i = 0; i < CHUNK; i++) {
            float h = fmaf(tv[i], w1, bb);
            h = fmaxf(h, 0.0f);
            accv[i] = fmaf(h, w2, accv[i]);
        }
    }
    #pragma unroll
    for (int i = 0; i < CHUNK; i++) {
        const float w  = tanhf(accv[i]);                   // in [-1, 1]
        const float sp = fmaxf(w, 0.0f) + log1pf(expf(-fabsf(w)));
        lv[i * 256 + tid] = sp;
    }
    __syncthreads();

    // --- up-sweep: pairwise sums, 11 levels (matches jax associative_scan) ---
    for (int k = 0; k < 11; k++) {
        const int half = (SS >> k) >> 1;
        const int o  = c_off[k];
        const int o1 = c_off[k + 1];
        for (int j = tid; j < half; j += 256)
            lv[o1 + j] = lv[o + 2 * j] + lv[o + 2 * j + 1];
        __syncthreads();
    }

    // --- down-sweep ---
    for (int k = 10; k >= 0; k--) {
        const int half = (SS >> k) >> 1;
        const int o  = c_off[k];
        const int o1 = c_off[k + 1];
        for (int j = tid; j < half; j += 256) {
            const float sn = lv[o1 + j];
            if (j >= 1) lv[o + 2 * j] = lv[o1 + j - 1] + lv[o + 2 * j];
            lv[o + 2 * j + 1] = sn;
        }
        __syncthreads();
    }

    const float total = lv[SS - 1];

    // --- per-s warp value (f32 IEEE divide, like ref), base, weights ---
    for (int i = 0; i < CHUNK; i++) {
        const int s = i * 256 + tid;
        const float w1f = lv[s] / total;
        wf[s] = w1f;
        const float pos = w1f * (float)(SS - 1);
        float fi0 = floorf(pos);
        if (fi0 < 0.0f) fi0 = 0.0f;
        if (fi0 > (float)(SS - 2)) fi0 = (float)(SS - 2);
        const int   i0   = (int)fi0;
        const float frac = pos - fi0;
        const float om   = 1.0f - frac;
        g_base[s] = i0 - RAD;
        #pragma unroll
        for (int m = 0; m < TAPS; m++) {
            const float k0 = (m < KW) ? skern[m]     : 0.0f;
            const float k1 = (m >= 1) ? skern[m - 1] : 0.0f;
            g_cw[s * TAPS + m] = om * k0 + frac * k1;
        }
    }
    __syncthreads();

    // --- smoothness loss: mean squared f32 2nd difference of warps ---
    double ssq = 0.0;
    for (int i = 0; i < CHUNK; i++) {
        const int s = i * 256 + tid;
        if (s <= SS - 3) {
            const float d1a = wf[s + 1] - wf[s];
            const float d1b = wf[s + 2] - wf[s + 1];
            const float d2  = d1b - d1a;
            ssq += (double)d2 * (double)d2;
        }
    }
    for (int off = 16; off; off >>= 1)
        ssq += __shfl_down_sync(0xffffffffu, ssq, off);
    if (lane == 0) red[wrp] = ssq;
    __syncthreads();
    if (tid == 0 && write_loss) {
        double v = 0.0;
        for (int wv = 0; wv < 8; wv++) v += red[wv];
        *loss_out = (float)(v / (double)(SS - 2));
    }
}

// ---------------------------------------------------------------------------
// Kernel B: fused smooth + warp interp, ROW-REUSE formulation.
// CTA = 1 batch x 16 s-rows x 512 feats. Two 8-s groups (tx>>7); each thread
// owns one float4 column and 8 s-accumulators in registers. Iterate over the
// group's distinct input rows (span ~34 instead of 8x26=208 loads): load each
// row's float4 ONCE, apply to all 8 accumulators via packed f32x2 FMA with
// pre-duplicated weights from smem. L1 traffic /6, FMA issue /2.
// ---------------------------------------------------------------------------
__global__ __launch_bounds__(256)
void warp_apply_kernel(const float* __restrict__ x, float* __restrict__ out)
{
    __shared__ int sbase[STILE];
    __shared__ int rofs[2][SPAN];                       // row offsets (16B units)
    __shared__ unsigned long long wtab[2][SPAN][8];     // weights dup-packed

    const int b  = blockIdx.y;
    const int s0 = blockIdx.x * STILE;
    const int tx = threadIdx.x;

    if (tx < STILE) sbase[tx] = g_base[s0 + tx];
    __syncthreads();

    // row offsets with symmetric reflection (premultiplied by FF/4)
    for (int idx = tx; idx < 2 * SPAN; idx += 256) {
        const int gg = idx / SPAN, i = idx % SPAN;
        int r = sbase[gg * 8] + i;
        r = (r < 0) ? (-1 - r) : ((r >= SS) ? (2 * SS - 1 - r) : r);
        rofs[gg][i] = r * (FF / 4);
    }
    // weight table: wtab[g][i][sl] = cw for tap (rmin_g + i) of s-row sl
    for (int idx = tx; idx < 2 * SPAN * 8; idx += 256) {
        const int gg  = idx / (SPAN * 8);
        const int rem = idx % (SPAN * 8);
        const int i   = rem / 8, sl = rem % 8;
        const int s   = gg * 8 + sl;
        const int m   = sbase[gg * 8] + i - sbase[s];
        const float w = (m >= 0 && m < TAPS) ? g_cw[(s0 + s) * TAPS + m] : 0.0f;
        const unsigned int wi = __float_as_uint(w);
        wtab[gg][i][sl] = ((unsigned long long)wi << 32) | wi;
    }
    __syncthreads();

    const int g  = tx >> 7;        // 8-s group
    const int f4 = tx & 127;       // float4 column
    int span = sbase[g * 8 + 7] + TAPS - sbase[g * 8];
    if (span > SPAN) span = SPAN;

    const ulonglong2* __restrict__ xb =
        (const ulonglong2*)(x + (size_t)b * SS * FF);

    unsigned long long accL[8], accH[8];
    #pragma unroll
    for (int s = 0; s < 8; s++) { accL[s] = 0ull; accH[s] = 0ull; }

    #pragma unroll 2
    for (int i = 0; i < span; i++) {
        const ulonglong2 vv = __ldg(xb + rofs[g][i] + f4);
        const ulonglong2* wr = (const ulonglong2*)&wtab[g][i][0];
        const ulonglong2 w01 = wr[0], w23 = wr[1], w45 = wr[2], w67 = wr[3];
        FMA_X2(accL[0], w01.x, vv.x);  FMA_X2(accH[0], w01.x, vv.y);
        FMA_X2(accL[1], w01.y, vv.x);  FMA_X2(accH[1], w01.y, vv.y);
        FMA_X2(accL[2], w23.x, vv.x);  FMA_X2(accH[2], w23.x, vv.y);
        FMA_X2(accL[3], w23.y, vv.x);  FMA_X2(accH[3], w23.y, vv.y);
        FMA_X2(accL[4], w45.x, vv.x);  FMA_X2(accH[4], w45.x, vv.y);
        FMA_X2(accL[5], w45.y, vv.x);  FMA_X2(accH[5], w45.y, vv.y);
        FMA_X2(accL[6], w67.x, vv.x);  FMA_X2(accH[6], w67.x, vv.y);
        FMA_X2(accL[7], w67.y, vv.x);  FMA_X2(accH[7], w67.y, vv.y);
    }

    ulonglong2* __restrict__ ob =
        (ulonglong2*)(out + (size_t)b * SS * FF);
    #pragma unroll
    for (int s = 0; s < 8; s++)
        ob[(size_t)(s0 + g * 8 + s) * (FF / 4) + f4] =
            make_ulonglong2(accL[s], accH[s]);
}

extern "C" void kernel_launch(void* const* d_in, const int* in_sizes, int n_in,
                              void* d_out, int out_size)
{
    const float* x  = (const float*)d_in[0];
    const float* W1 = (const float*)d_in[1];
    const float* b1 = (const float*)d_in[2];
    const float* W2 = (const float*)d_in[3];
    const float* b2 = (const float*)d_in[4];
    float* out = (float*)d_out;

    const size_t warped_elems = (size_t)BS * SS * FF;
    const int write_loss = ((size_t)out_size > warped_elems) ? 1 : 0;
    float* loss_ptr = out + warped_elems;   // scalar loss after warped tensor

    warp_setup_kernel<<<1, 256>>>(W1, b1, W2, b2, loss_ptr, write_loss);

    dim3 grid(SS / STILE, BS);
    warp_apply_kernel<<<grid, 256>>>(x, out);
}

// round 17
// speedup vs baseline: 1.6818x; 1.2620x over previous
#include <cuda_runtime.h>
#include <math.h>

#define BS   32
#define SS   2048
#define FF   512
#define RAD  12
#define KW   25
#define TAPS 26
#define CHUNK 8            // s-values per thread in setup kernel (256 thr)
#define SPAN 96            // max input-row window per 8-s group

// Scratch (no cudaMalloc allowed): combined 26-tap weights and base row per s.
__device__ float g_cw[SS * TAPS];
__device__ int   g_base[SS];

// Level offsets for the associative-scan pyramid (sizes 2048,1024,...,1).
__constant__ int c_off[12] = {0, 2048, 3072, 3584, 3840, 3968, 4032,
                              4064, 4080, 4088, 4092, 4094};

// packed fp32x2 fma (per-lane IEEE identical to fmaf)
#define FMA_X2(acc, w, v) \
    asm("fma.rn.f32x2 %0, %1, %2, %0;" : "+l"(acc) : "l"(w), "l"(v))

struct GaussK { float k[KW]; };   // passed by value: computed on host in f64

// ---------------------------------------------------------------------------
// Kernel A: tiny MLP (f32, j-outer) -> tanh -> softplus -> f32 ASSOCIATIVE-
// SCAN cumsum replicating XLA's exact add-pairing -> warp positions +
// combined smoothing/interp weights + smoothness loss. No FP64 transcendentals
// on device (gauss kernel comes precomputed from host).
// ---------------------------------------------------------------------------
__global__ __launch_bounds__(256)
void warp_setup_kernel(const float* __restrict__ W1,
                       const float* __restrict__ b1,
                       const float* __restrict__ W2,
                       const float* __restrict__ b2,
                       float* __restrict__ loss_out,
                       int write_loss,
                       GaussK gk)
{
    __shared__ float lv[4095];        // scan pyramid, 16 KB
    __shared__ float wf[SS];          // f32 warp values
    __shared__ double red[8];

    const int tid  = threadIdx.x;     // 0..255
    const int lane = tid & 31;
    const int wrp  = tid >> 5;

    // --- f32 MLP: j-outer so W1/b1/W2 are loaded once per j. ---
    float tv[CHUNK], accv[CHUNK];
    #pragma unroll
    for (int i = 0; i < CHUNK; i++) {
        tv[i]   = (float)(i * 256 + tid) / (float)(SS - 1);
        accv[i] = b2[0];
    }
    for (int j = 0; j < 64; j++) {
        const float w1 = W1[j], bb = b1[j], w2 = W2[j];
        #pragma unroll
        for (int i = 0; i < CHUNK; i++) {
            float h = fmaf(tv[i], w1, bb);
            h = fmaxf(h, 0.0f);
            accv[i] = fmaf(h, w2, accv[i]);
        }
    }
    #pragma unroll
    for (int i = 0; i < CHUNK; i++) {
        const float w  = tanhf(accv[i]);                   // in [-1, 1]
        const float sp = fmaxf(w, 0.0f) + log1pf(expf(-fabsf(w)));
        lv[i * 256 + tid] = sp;
    }
    __syncthreads();

    // --- up-sweep: pairwise sums, 11 levels (matches jax associative_scan) ---
    for (int k = 0; k < 11; k++) {
        const int half = (SS >> k) >> 1;
        const int o  = c_off[k];
        const int o1 = c_off[k + 1];
        for (int j = tid; j < half; j += 256)
            lv[o1 + j] = lv[o + 2 * j] + lv[o + 2 * j + 1];
        __syncthreads();
    }

    // --- down-sweep ---
    for (int k = 10; k >= 0; k--) {
        const int half = (SS >> k) >> 1;
        const int o  = c_off[k];
        const int o1 = c_off[k + 1];
        for (int j = tid; j < half; j += 256) {
            const float sn = lv[o1 + j];
            if (j >= 1) lv[o + 2 * j] = lv[o1 + j - 1] + lv[o + 2 * j];
            lv[o + 2 * j + 1] = sn;
        }
        __syncthreads();
    }

    const float total = lv[SS - 1];

    // --- per-s warp value (f32 IEEE divide, like ref), base, weights ---
    for (int i = 0; i < CHUNK; i++) {
        const int s = i * 256 + tid;
        const float w1f = lv[s] / total;
        wf[s] = w1f;
        const float pos = w1f * (float)(SS - 1);
        float fi0 = floorf(pos);
        if (fi0 < 0.0f) fi0 = 0.0f;
        if (fi0 > (float)(SS - 2)) fi0 = (float)(SS - 2);
        const int   i0   = (int)fi0;
        const float frac = pos - fi0;
        const float om   = 1.0f - frac;
        g_base[s] = i0 - RAD;
        #pragma unroll
        for (int m = 0; m < TAPS; m++) {
            const float k0 = (m < KW) ? gk.k[m]     : 0.0f;
            const float k1 = (m >= 1) ? gk.k[m - 1] : 0.0f;
            g_cw[s * TAPS + m] = om * k0 + frac * k1;
        }
    }
    __syncthreads();

    // --- smoothness loss: mean squared f32 2nd difference of warps ---
    double ssq = 0.0;
    for (int i = 0; i < CHUNK; i++) {
        const int s = i * 256 + tid;
        if (s <= SS - 3) {
            const float d1a = wf[s + 1] - wf[s];
            const float d1b = wf[s + 2] - wf[s + 1];
            const float d2  = d1b - d1a;
            ssq += (double)d2 * (double)d2;
        }
    }
    for (int off = 16; off; off >>= 1)
        ssq += __shfl_down_sync(0xffffffffu, ssq, off);
    if (lane == 0) red[wrp] = ssq;
    __syncthreads();
    if (tid == 0 && write_loss) {
        double v = 0.0;
        for (int wv = 0; wv < 8; wv++) v += red[wv];
        *loss_out = (float)(v / (double)(SS - 2));
    }
}

// ---------------------------------------------------------------------------
// Kernel B: fused smooth + warp interp, ROW-REUSE formulation.
// CTA = 1 batch x 8 s-rows x 512 feats (128 threads, one group -> finer
// register granularity: ~8 CTAs/SM = 50% occ). Each thread owns one float4
// column and 8 s-accumulators. Iterate over the group's distinct input rows:
// load each row's float4 ONCE, apply to all 8 accumulators via packed f32x2
// FMA with pre-duplicated weights from smem.
// ---------------------------------------------------------------------------
__global__ __launch_bounds__(128)
void warp_apply_kernel(const float* __restrict__ x, float* __restrict__ out)
{
    __shared__ int sbase[8];
    __shared__ int rofs[SPAN];                       // row offsets (16B units)
    __shared__ unsigned long long wtab[SPAN][8];     // weights dup-packed

    const int b  = blockIdx.y;
    const int s0 = blockIdx.x * 8;
    const int tx = threadIdx.x;

    if (tx < 8) sbase[tx] = g_base[s0 + tx];
    __syncthreads();
    const int base0 = sbase[0];

    // row offsets with symmetric reflection (premultiplied by FF/4)
    for (int i = tx; i < SPAN; i += 128) {
        int r = base0 + i;
        r = (r < 0) ? (-1 - r) : ((r >= SS) ? (2 * SS - 1 - r) : r);
        rofs[i] = r * (FF / 4);
    }
    // weight table: wtab[i][sl] = cw for input row (base0 + i) in s-row sl
    for (int idx = tx; idx < SPAN * 8; idx += 128) {
        const int i  = idx >> 3, sl = idx & 7;
        const int m  = base0 + i - sbase[sl];
        const float w = (m >= 0 && m < TAPS) ? g_cw[(s0 + sl) * TAPS + m] : 0.0f;
        const unsigned int wi = __float_as_uint(w);
        wtab[i][sl] = ((unsigned long long)wi << 32) | wi;
    }
    __syncthreads();

    int span = sbase[7] + TAPS - base0;
    if (span > SPAN) span = SPAN;

    const ulonglong2* __restrict__ xb =
        (const ulonglong2*)(x + (size_t)b * SS * FF);

    unsigned long long accL[8], accH[8];
    #pragma unroll
    for (int s = 0; s < 8; s++) { accL[s] = 0ull; accH[s] = 0ull; }

    for (int i = 0; i < span; i++) {
        const ulonglong2 vv = __ldg(xb + rofs[i] + tx);
        const ulonglong2* wr = (const ulonglong2*)&wtab[i][0];
        const ulonglong2 w01 = wr[0], w23 = wr[1], w45 = wr[2], w67 = wr[3];
        FMA_X2(accL[0], w01.x, vv.x);  FMA_X2(accH[0], w01.x, vv.y);
        FMA_X2(accL[1], w01.y, vv.x);  FMA_X2(accH[1], w01.y, vv.y);
        FMA_X2(accL[2], w23.x, vv.x);  FMA_X2(accH[2], w23.x, vv.y);
        FMA_X2(accL[3], w23.y, vv.x);  FMA_X2(accH[3], w23.y, vv.y);
        FMA_X2(accL[4], w45.x, vv.x);  FMA_X2(accH[4], w45.x, vv.y);
        FMA_X2(accL[5], w45.y, vv.x);  FMA_X2(accH[5], w45.y, vv.y);
        FMA_X2(accL[6], w67.x, vv.x);  FMA_X2(accH[6], w67.x, vv.y);
        FMA_X2(accL[7], w67.y, vv.x);  FMA_X2(accH[7], w67.y, vv.y);
    }

    ulonglong2* __restrict__ ob =
        (ulonglong2*)(out + (size_t)b * SS * FF);
    #pragma unroll
    for (int s = 0; s < 8; s++)
        ob[(size_t)(s0 + s) * (FF / 4) + tx] = make_ulonglong2(accL[s], accH[s]);
}

extern "C" void kernel_launch(void* const* d_in, const int* in_sizes, int n_in,
                              void* d_out, int out_size)
{
    const float* x  = (const float*)d_in[0];
    const float* W1 = (const float*)d_in[1];
    const float* b1 = (const float*)d_in[2];
    const float* W2 = (const float*)d_in[3];
    const float* b2 = (const float*)d_in[4];
    float* out = (float*)d_out;

    // gaussian kernel computed on HOST in f64 (bit-identical to device f64
    // path used in the R11/R12 passing runs), passed by value.
    GaussK gk;
    {
        double kd[KW], sum = 0.0;
        for (int m = 0; m < KW; m++) {
            double xx = (double)(m - RAD) / 3.0;
            kd[m] = exp(-0.5 * xx * xx);
            sum += kd[m];
        }
        for (int m = 0; m < KW; m++) gk.k[m] = (float)(kd[m] / sum);
    }

    const size_t warped_elems = (size_t)BS * SS * FF;
    const int write_loss = ((size_t)out_size > warped_elems) ? 1 : 0;
    float* loss_ptr = out + warped_elems;   // scalar loss after warped tensor

    warp_setup_kernel<<<1, 256>>>(W1, b1, W2, b2, loss_ptr, write_loss, gk);

    dim3 grid(SS / 8, BS);
    warp_apply_kernel<<<grid, 128>>>(x, out);
}